// round 12
// baseline (speedup 1.0000x reference)
#include <cuda_runtime.h>

// NeRF importance sampler — push-model + fused group-owner epilogue.
//   inputs : rays_o[N,3], rays_d[N,3], z_vals[N,64] (sorted), weights[N,64]
//   outputs: pts[N,192,3] | z_all[N,192] | z_samples[N,128]  (flat concat)
//
// One warp per ray, 8 warps/block, 8 blocks/SM. u_j = j/127 uniform =>
// interval k owns samples j in [B_k, B_{k+1}), B_k = clamp(ceil(127*cdf_k),128).
// Lane l owns intervals 2l, 2l+1 (params in registers), generates its samples,
// writes z_samples straight to gmem, scatters each sample into its merged zal
// position (pos = j + lo + (zvR <= v)), counts #{v < zvR} in-flight, and
// places its right-edge z_val at k+1 + B_k + count_lt. Complementary compares
// keep the 192 positions a permutation.
// Epilogue: lane owns point-group g (4 consecutive points): one LDS.128 of
// zal feeds BOTH the z_all copy and 12 FFMA -> 3 STG.128 of pts (stride-48
// per lane, but adjacent lanes tile every 128B line fully => pure writes).

#define NS   64
#define NI   128
#define NT   192
#define WPB  8

__global__ __launch_bounds__(256, 8)
void importance_sampler_kernel(const float* __restrict__ rays_o,
                               const float* __restrict__ rays_d,
                               const float* __restrict__ z_vals,
                               const float* __restrict__ weights,
                               float* __restrict__ out_pts,    // [N,192,3]
                               float* __restrict__ out_zall,   // [N,192]
                               float* __restrict__ out_zs,     // [N,128]
                               int n_rays)
{
    __shared__ __align__(16) float sbuf[WPB][NT];   // zal only

    const int warp = threadIdx.x >> 5;
    const int lane = threadIdx.x & 31;
    const int ray  = blockIdx.x * WPB + warp;
    if (ray >= n_rays) return;

    float* zal = sbuf[warp];

    // ---- Phase 1: loads + CDF scan (all in registers) ---------------------
    const float2 z2 = ((const float2*)(z_vals + (size_t)ray * NS))[lane];
    const float2 w2 = ((const float2*)(weights + (size_t)ray * NS))[lane];
    const float wnx = __shfl_down_sync(0xffffffffu, w2.x, 1);   // wrow[2l+2]

    // w[j] = weights[j+1]+1e-5, j=0..61; lane l<31 owns j=2l (wa), 2l+1 (wb)
    float wa = 0.f, wb = 0.f;
    if (lane < 31) {
        wa = w2.y + 1e-5f;
        wb = wnx  + 1e-5f;
    }
    const float local = wa + wb;
    float s = local;
    #pragma unroll
    for (int off = 1; off < 32; off <<= 1) {
        float up = __shfl_up_sync(0xffffffffu, s, off);
        if (lane >= off) s += up;
    }
    const float inv_total = 1.0f / __shfl_sync(0xffffffffu, s, 31);
    const float excl = s - local;

    // cdf[2l+1] = c1, cdf[2l+2] = c2 (valid for lane<31)
    float c1 = 0.f, c2 = 0.f;
    if (lane < 31) {
        c1 = (excl + wa) * inv_total;
        c2 = (excl + local) * inv_total;
    }

    // ---- Phase 2: per-lane interval parameters (registers only) -----------
    const float znx = __shfl_down_sync(0xffffffffu, z2.x, 1);   // zv[2l+2]
    const float m0  = 0.5f * (z2.x + z2.y);                     // mid[2l]
    const float m1  = 0.5f * (z2.y + znx);                      // mid[2l+1] (l<31)
    float cprev = __shfl_up_sync(0xffffffffu, c2, 1);           // cdf[2l]
    if (lane == 0) cprev = 0.f;
    const float mnext = __shfl_down_sync(0xffffffffu, m0, 1);   // mid[2l+2] (l<31)

    // Sample-range boundaries B (monotone since cdf strictly increases)
    const int bA = min((int)ceilf(cprev * 127.0f), 128);        // B[2l]
    int bB = 128, bC = 128;                                     // lane 31: A=[bA,128)
    float SA = 0.f, SB = 0.f;                                   // lane 31: v = mid[62]
    if (lane < 31) {
        bB = min((int)ceilf(c1 * 127.0f), 128);                 // B[2l+1]
        bC = min((int)ceilf(c2 * 127.0f), 128);                 // B[2l+2]
        float dA = c1 - cprev; if (dA < 1e-5f) dA = 1.0f;
        float dB = c2 - c1;    if (dB < 1e-5f) dB = 1.0f;
        SA = (m1 - m0) / dA;
        SB = (mnext - m1) / dB;
    }

    // ---- Phase 3: generate samples; z_samples straight to gmem ------------
    float* ozs = out_zs + (size_t)ray * NI;
    if (lane == 0) zal[0] = z2.x;              // zv[0] always ranks first

    // interval k = 2l: samples [bA, bB), right edge zv[2l+1] = z2.y, lo = 2l+1
    {
        int cnt_ge = 0;
        for (int j = bA; j < bB; j++) {
            const float u = (float)j * (1.0f / 127.0f);
            const float v = fmaf(u - cprev, SA, m0);
            ozs[j] = v;                         // scattered STG.32 (row fully covered)
            const int ge = (z2.y <= v) ? 1 : 0;
            cnt_ge += ge;
            zal[j + 2 * lane + 1 + ge] = v;
        }
        // place zv[2l+1]: pos = (2l+1) + B[2l] + #{v < zv[2l+1]}
        zal[2 * lane + 1 + bA + (bB - bA) - cnt_ge] = z2.y;
    }
    // interval k = 2l+1 (lane<31): samples [bB, bC), right edge zv[2l+2] = znx
    {
        int cnt_ge = 0;
        for (int j = bB; j < bC; j++) {
            const float u = (float)j * (1.0f / 127.0f);
            const float v = fmaf(u - c1, SB, m1);
            ozs[j] = v;
            const int ge = (znx <= v) ? 1 : 0;
            cnt_ge += ge;
            zal[j + 2 * lane + 2 + ge] = v;
        }
        if (lane < 31)
            zal[2 * lane + 2 + bB + (bC - bB) - cnt_ge] = znx;
    }
    __syncwarp();

    // ---- Fused epilogue: z_all copy + pts, one LDS.128 per point-group ----
    const float ox = rays_o[3 * (size_t)ray + 0];
    const float oy = rays_o[3 * (size_t)ray + 1];
    const float oz = rays_o[3 * (size_t)ray + 2];
    const float dx = rays_d[3 * (size_t)ray + 0];
    const float dy = rays_d[3 * (size_t)ray + 1];
    const float dz = rays_d[3 * (size_t)ray + 2];

    float4* a4   = (float4*)(out_zall + (size_t)ray * NT);     // 48 x float4
    float*  optr = out_pts + (size_t)ray * (NT * 3);
    const float4* z4s = (const float4*)zal;

    #pragma unroll
    for (int t = 0; t < 2; t++) {
        if (t == 0 || lane < 16) {
            const int g = lane + 32 * t;          // point-group 0..47
            const float4 z4 = z4s[g];
            a4[g] = z4;                           // z_all out, coalesced

            float4* dst = (float4*)(optr + 12 * g);
            float4 A, Bq, C;                      // sequential to cap registers
            A.x = fmaf(dx, z4.x, ox); A.y = fmaf(dy, z4.x, oy);
            A.z = fmaf(dz, z4.x, oz); A.w = fmaf(dx, z4.y, ox);
            dst[0] = A;
            Bq.x = fmaf(dy, z4.y, oy); Bq.y = fmaf(dz, z4.y, oz);
            Bq.z = fmaf(dx, z4.z, ox); Bq.w = fmaf(dy, z4.z, oy);
            dst[1] = Bq;
            C.x = fmaf(dz, z4.z, oz); C.y = fmaf(dx, z4.w, ox);
            C.z = fmaf(dy, z4.w, oy); C.w = fmaf(dz, z4.w, oz);
            dst[2] = C;
        }
    }
}

extern "C" void kernel_launch(void* const* d_in, const int* in_sizes, int n_in,
                              void* d_out, int out_size)
{
    const float* rays_o  = (const float*)d_in[0];
    const float* rays_d  = (const float*)d_in[1];
    const float* z_vals  = (const float*)d_in[2];
    const float* weights = (const float*)d_in[3];

    const int n_rays = in_sizes[0] / 3;

    float* out_pts  = (float*)d_out;
    float* out_zall = out_pts + (size_t)n_rays * (NT * 3);
    float* out_zs   = out_zall + (size_t)n_rays * NT;

    const int blocks = (n_rays + WPB - 1) / WPB;
    importance_sampler_kernel<<<blocks, 256>>>(rays_o, rays_d, z_vals, weights,
                                               out_pts, out_zall, out_zs, n_rays);
}

// round 13
// speedup vs baseline: 1.2605x; 1.2605x over previous
#include <cuda_runtime.h>

// NeRF importance sampler — push-model + shared-transposed epilogue.
//   inputs : rays_o[N,3], rays_d[N,3], z_vals[N,64] (sorted), weights[N,64]
//   outputs: pts[N,192,3] | z_all[N,192] | z_samples[N,128]  (flat concat)
//
// One warp per ray, 8 warps/block, 8 blocks/SM. u_j = j/127 uniform =>
// interval k owns samples j in [B_k, B_{k+1}), B_k = clamp(ceil(127*cdf_k),128).
// Lane l owns intervals 2l, 2l+1 (params in registers), generates its samples,
// scatters them into zs and into their merged zal position
// (pos = j + lo + (zvR <= v)), counts #{v < zvR} in-flight, and places its
// right-edge z_val at k+1 + B_k + count_lt. Complementary compares keep the
// 192 positions a permutation.
// Epilogue: lane owns point-group g (4 consecutive points): one LDS.128 of
// zal feeds the z_all store AND 12 FFMA -> 3 STS.128 into a natural-layout
// staging buffer (bank-disjoint), then 4.5 coalesced LDS.128+STG.128 to gmem.
// ALL global stores are warp-coalesced 128-bit — no partial-sector lines.

#define NS   64
#define NI   128
#define NT   192
#define WPB  8

__global__ __launch_bounds__(256, 8)
void importance_sampler_kernel(const float* __restrict__ rays_o,
                               const float* __restrict__ rays_d,
                               const float* __restrict__ z_vals,
                               const float* __restrict__ weights,
                               float* __restrict__ out_pts,    // [N,192,3]
                               float* __restrict__ out_zall,   // [N,192]
                               float* __restrict__ out_zs,     // [N,128]
                               int n_rays)
{
    __shared__ __align__(16) float sbuf[WPB][768];
    // per warp: zs [0,128) ; zal [576,768) ; pst [0,576) after zs copied out

    const int warp = threadIdx.x >> 5;
    const int lane = threadIdx.x & 31;
    const int ray  = blockIdx.x * WPB + warp;
    if (ray >= n_rays) return;

    float* buf = sbuf[warp];
    float* zs  = buf;          // [0,128)
    float* zal = buf + 576;    // [576,768)
    float* pst = buf;          // [0,576), reused

    // ---- Phase 1: loads + CDF scan (all in registers) ---------------------
    const float2 z2 = ((const float2*)(z_vals + (size_t)ray * NS))[lane];
    const float2 w2 = ((const float2*)(weights + (size_t)ray * NS))[lane];
    const float wnx = __shfl_down_sync(0xffffffffu, w2.x, 1);   // wrow[2l+2]

    // w[j] = weights[j+1]+1e-5, j=0..61; lane l<31 owns j=2l (wa), 2l+1 (wb)
    float wa = 0.f, wb = 0.f;
    if (lane < 31) {
        wa = w2.y + 1e-5f;
        wb = wnx  + 1e-5f;
    }
    const float local = wa + wb;
    float s = local;
    #pragma unroll
    for (int off = 1; off < 32; off <<= 1) {
        float up = __shfl_up_sync(0xffffffffu, s, off);
        if (lane >= off) s += up;
    }
    const float inv_total = 1.0f / __shfl_sync(0xffffffffu, s, 31);
    const float excl = s - local;

    // cdf[2l+1] = c1, cdf[2l+2] = c2 (valid for lane<31)
    float c1 = 0.f, c2 = 0.f;
    if (lane < 31) {
        c1 = (excl + wa) * inv_total;
        c2 = (excl + local) * inv_total;
    }

    // ---- Phase 2: per-lane interval parameters (registers only) -----------
    const float znx = __shfl_down_sync(0xffffffffu, z2.x, 1);   // zv[2l+2]
    const float m0  = 0.5f * (z2.x + z2.y);                     // mid[2l]
    const float m1  = 0.5f * (z2.y + znx);                      // mid[2l+1] (l<31)
    float cprev = __shfl_up_sync(0xffffffffu, c2, 1);           // cdf[2l]
    if (lane == 0) cprev = 0.f;
    const float mnext = __shfl_down_sync(0xffffffffu, m0, 1);   // mid[2l+2] (l<31)

    // Sample-range boundaries B (monotone since cdf strictly increases)
    const int bA = min((int)ceilf(cprev * 127.0f), 128);        // B[2l]
    int bB = 128, bC = 128;                                     // lane 31: A=[bA,128)
    float SA = 0.f, SB = 0.f;                                   // lane 31: v = mid[62]
    if (lane < 31) {
        bB = min((int)ceilf(c1 * 127.0f), 128);                 // B[2l+1]
        bC = min((int)ceilf(c2 * 127.0f), 128);                 // B[2l+2]
        float dA = c1 - cprev; if (dA < 1e-5f) dA = 1.0f;
        float dB = c2 - c1;    if (dB < 1e-5f) dB = 1.0f;
        SA = (m1 - m0) / dA;
        SB = (mnext - m1) / dB;
    }

    // ---- Phase 3: generate samples, scatter into zs and merged zal --------
    if (lane == 0) zal[0] = z2.x;              // zv[0] always ranks first

    // interval k = 2l: samples [bA, bB), right edge zv[2l+1] = z2.y, lo = 2l+1
    {
        int cnt_ge = 0;
        for (int j = bA; j < bB; j++) {
            const float u = (float)j * (1.0f / 127.0f);
            const float v = fmaf(u - cprev, SA, m0);
            zs[j] = v;
            const int ge = (z2.y <= v) ? 1 : 0;
            cnt_ge += ge;
            zal[j + 2 * lane + 1 + ge] = v;
        }
        // place zv[2l+1]: pos = (2l+1) + B[2l] + #{v < zv[2l+1]}
        zal[2 * lane + 1 + bA + (bB - bA) - cnt_ge] = z2.y;
    }
    // interval k = 2l+1 (lane<31): samples [bB, bC), right edge zv[2l+2] = znx
    {
        int cnt_ge = 0;
        for (int j = bB; j < bC; j++) {
            const float u = (float)j * (1.0f / 127.0f);
            const float v = fmaf(u - c1, SB, m1);
            zs[j] = v;
            const int ge = (znx <= v) ? 1 : 0;
            cnt_ge += ge;
            zal[j + 2 * lane + 2 + ge] = v;
        }
        if (lane < 31)
            zal[2 * lane + 2 + bB + (bC - bB) - cnt_ge] = znx;
    }
    __syncwarp();

    // ---- z_samples out (float4, coalesced), then free zs region -----------
    ((float4*)(out_zs + (size_t)ray * NI))[lane] = ((const float4*)zs)[lane];
    __syncwarp();   // zs reads complete before pst overwrites [0,576)

    // ---- Epilogue A: group-owner compute + z_all store + STS.128 staging --
    const float ox = rays_o[3 * (size_t)ray + 0];
    const float oy = rays_o[3 * (size_t)ray + 1];
    const float oz = rays_o[3 * (size_t)ray + 2];
    const float dx = rays_d[3 * (size_t)ray + 0];
    const float dy = rays_d[3 * (size_t)ray + 1];
    const float dz = rays_d[3 * (size_t)ray + 2];

    float4* a4 = (float4*)(out_zall + (size_t)ray * NT);       // 48 x float4
    const float4* zal4 = (const float4*)zal;
    float4* pst4 = (float4*)pst;

    #pragma unroll
    for (int t = 0; t < 2; t++) {
        if (t == 0 || lane < 16) {
            const int g = lane + 32 * t;          // point-group 0..47
            const float4 z4 = zal4[g];
            a4[g] = z4;                           // z_all out, coalesced

            float4 A, Bq, C;                      // natural layout: float4 3g..3g+2
            A.x  = fmaf(dx, z4.x, ox); A.y  = fmaf(dy, z4.x, oy);
            A.z  = fmaf(dz, z4.x, oz); A.w  = fmaf(dx, z4.y, ox);
            pst4[3 * g + 0] = A;
            Bq.x = fmaf(dy, z4.y, oy); Bq.y = fmaf(dz, z4.y, oz);
            Bq.z = fmaf(dx, z4.z, ox); Bq.w = fmaf(dy, z4.z, oy);
            pst4[3 * g + 1] = Bq;
            C.x  = fmaf(dz, z4.z, oz); C.y  = fmaf(dx, z4.w, ox);
            C.z  = fmaf(dy, z4.w, oy); C.w  = fmaf(dz, z4.w, oz);
            pst4[3 * g + 2] = C;
        }
    }
    __syncwarp();

    // ---- Epilogue B: coalesced LDS.128 + STG.128 copy of pts --------------
    float4* o4 = (float4*)(out_pts + (size_t)ray * (NT * 3));  // 144 x float4
    #pragma unroll
    for (int t = 0; t < 5; t++) {
        if (t < 4 || lane < 16) {
            const int m = lane + 32 * t;
            o4[m] = pst4[m];
        }
    }
}

extern "C" void kernel_launch(void* const* d_in, const int* in_sizes, int n_in,
                              void* d_out, int out_size)
{
    const float* rays_o  = (const float*)d_in[0];
    const float* rays_d  = (const float*)d_in[1];
    const float* z_vals  = (const float*)d_in[2];
    const float* weights = (const float*)d_in[3];

    const int n_rays = in_sizes[0] / 3;

    float* out_pts  = (float*)d_out;
    float* out_zall = out_pts + (size_t)n_rays * (NT * 3);
    float* out_zs   = out_zall + (size_t)n_rays * NT;

    const int blocks = (n_rays + WPB - 1) / WPB;
    importance_sampler_kernel<<<blocks, 256>>>(rays_o, rays_d, z_vals, weights,
                                               out_pts, out_zall, out_zs, n_rays);
}

// round 15
// speedup vs baseline: 1.2796x; 1.0151x over previous
#include <cuda_runtime.h>

// NeRF importance sampler — push-model + shared-transposed epilogue,
// with all global-load latency hoisted to kernel start.
//   inputs : rays_o[N,3], rays_d[N,3], z_vals[N,64] (sorted), weights[N,64]
//   outputs: pts[N,192,3] | z_all[N,192] | z_samples[N,128]  (flat concat)
//
// One warp per ray, 8 warps/block, 8 blocks/SM. u_j = j/127 uniform =>
// interval k owns samples j in [B_k, B_{k+1}), B_k = clamp(ceil(127*cdf_k),128).
// Lane l owns intervals 2l, 2l+1 (params in registers), generates its samples,
// scatters them into zs and into their merged zal position
// (pos = j + lo + (zvR <= v)); right edge placed at k+1 + B_k + count_lt.
// Complementary compares keep the 192 positions a permutation.
// o/d are loaded by lanes 0..5 at kernel entry and stashed in shared (keeps
// them off the register live-range and their DRAM latency off the epilogue's
// critical path). All global stores are warp-coalesced 128-bit.

#define NS   64
#define NI   128
#define NT   192
#define WPB  8

__global__ __launch_bounds__(256, 8)
void importance_sampler_kernel(const float* __restrict__ rays_o,
                               const float* __restrict__ rays_d,
                               const float* __restrict__ z_vals,
                               const float* __restrict__ weights,
                               float* __restrict__ out_pts,    // [N,192,3]
                               float* __restrict__ out_zall,   // [N,192]
                               float* __restrict__ out_zs,     // [N,128]
                               int n_rays)
{
    __shared__ __align__(16) float sbuf[WPB][776];
    // per warp: zs [0,128) ; zal [576,768) ; od [768,776) ; pst [0,576) reused

    const int warp = threadIdx.x >> 5;
    const int lane = threadIdx.x & 31;
    const int ray  = blockIdx.x * WPB + warp;
    if (ray >= n_rays) return;

    float* buf = sbuf[warp];
    float* zs  = buf;          // [0,128)
    float* zal = buf + 576;    // [576,768)
    float* od  = buf + 768;    // [768,774): ox oy oz dx dy dz
    float* pst = buf;          // [0,576), reused

    // ---- Hoisted input loads (issue everything before any compute) --------
    if (lane < 6) {
        const float v = (lane < 3) ? rays_o[3 * (size_t)ray + lane]
                                   : rays_d[3 * (size_t)ray + (lane - 3)];
        od[lane] = v;
    }
    const float2 z2 = ((const float2*)(z_vals + (size_t)ray * NS))[lane];
    const float2 w2 = ((const float2*)(weights + (size_t)ray * NS))[lane];

    // ---- Phase 1: CDF scan (all in registers) -----------------------------
    const float wnx = __shfl_down_sync(0xffffffffu, w2.x, 1);   // wrow[2l+2]

    // w[j] = weights[j+1]+1e-5, j=0..61; lane l<31 owns j=2l (wa), 2l+1 (wb)
    float wa = 0.f, wb = 0.f;
    if (lane < 31) {
        wa = w2.y + 1e-5f;
        wb = wnx  + 1e-5f;
    }
    const float local = wa + wb;
    float s = local;
    #pragma unroll
    for (int off = 1; off < 32; off <<= 1) {
        float up = __shfl_up_sync(0xffffffffu, s, off);
        if (lane >= off) s += up;
    }
    const float inv_total = 1.0f / __shfl_sync(0xffffffffu, s, 31);
    const float excl = s - local;

    // cdf[2l+1] = c1, cdf[2l+2] = c2 (valid for lane<31)
    float c1 = 0.f, c2 = 0.f;
    if (lane < 31) {
        c1 = (excl + wa) * inv_total;
        c2 = (excl + local) * inv_total;
    }

    // ---- Phase 2: per-lane interval parameters (registers only) -----------
    const float znx = __shfl_down_sync(0xffffffffu, z2.x, 1);   // zv[2l+2]
    const float m0  = 0.5f * (z2.x + z2.y);                     // mid[2l]
    const float m1  = 0.5f * (z2.y + znx);                      // mid[2l+1] (l<31)
    float cprev = __shfl_up_sync(0xffffffffu, c2, 1);           // cdf[2l]
    if (lane == 0) cprev = 0.f;
    const float mnext = __shfl_down_sync(0xffffffffu, m0, 1);   // mid[2l+2] (l<31)

    // Sample-range boundaries B (monotone since cdf strictly increases)
    const int bA = min((int)ceilf(cprev * 127.0f), 128);        // B[2l]
    int bB = 128, bC = 128;                                     // lane 31: A=[bA,128)
    float SA = 0.f, SB = 0.f;                                   // lane 31: v = mid[62]
    if (lane < 31) {
        bB = min((int)ceilf(c1 * 127.0f), 128);                 // B[2l+1]
        bC = min((int)ceilf(c2 * 127.0f), 128);                 // B[2l+2]
        float dA = c1 - cprev; if (dA < 1e-5f) dA = 1.0f;
        float dB = c2 - c1;    if (dB < 1e-5f) dB = 1.0f;
        SA = (m1 - m0) / dA;
        SB = (mnext - m1) / dB;
    }

    // ---- Phase 3: generate samples, scatter into zs and merged zal --------
    if (lane == 0) zal[0] = z2.x;              // zv[0] always ranks first

    // interval k = 2l: samples [bA, bB), right edge zv[2l+1] = z2.y, lo = 2l+1
    {
        int cnt_ge = 0;
        for (int j = bA; j < bB; j++) {
            const float u = (float)j * (1.0f / 127.0f);
            const float v = fmaf(u - cprev, SA, m0);
            zs[j] = v;
            const int ge = (z2.y <= v) ? 1 : 0;
            cnt_ge += ge;
            zal[j + 2 * lane + 1 + ge] = v;
        }
        // place zv[2l+1]: pos = (2l+1) + B[2l] + #{v < zv[2l+1]}
        zal[2 * lane + 1 + bA + (bB - bA) - cnt_ge] = z2.y;
    }
    // interval k = 2l+1 (lane<31): samples [bB, bC), right edge zv[2l+2] = znx
    {
        int cnt_ge = 0;
        for (int j = bB; j < bC; j++) {
            const float u = (float)j * (1.0f / 127.0f);
            const float v = fmaf(u - c1, SB, m1);
            zs[j] = v;
            const int ge = (znx <= v) ? 1 : 0;
            cnt_ge += ge;
            zal[j + 2 * lane + 2 + ge] = v;
        }
        if (lane < 31)
            zal[2 * lane + 2 + bB + (bC - bB) - cnt_ge] = znx;
    }
    __syncwarp();

    // ---- z_samples out (float4, coalesced), then free zs region -----------
    ((float4*)(out_zs + (size_t)ray * NI))[lane] = ((const float4*)zs)[lane];

    // o/d from shared (broadcast LDS, latency long since hidden)
    const float ox = od[0], oy = od[1], oz = od[2];
    const float dx = od[3], dy = od[4], dz = od[5];
    __syncwarp();   // zs reads complete before pst overwrites [0,576)

    // ---- Epilogue A: group-owner compute + z_all store + STS.128 staging --
    float4* a4 = (float4*)(out_zall + (size_t)ray * NT);       // 48 x float4
    const float4* zal4 = (const float4*)zal;
    float4* pst4 = (float4*)pst;

    #pragma unroll
    for (int t = 0; t < 2; t++) {
        if (t == 0 || lane < 16) {
            const int g = lane + 32 * t;          // point-group 0..47
            const float4 z4 = zal4[g];
            a4[g] = z4;                           // z_all out, coalesced

            float4 A, Bq, C;                      // natural layout: float4 3g..3g+2
            A.x  = fmaf(dx, z4.x, ox); A.y  = fmaf(dy, z4.x, oy);
            A.z  = fmaf(dz, z4.x, oz); A.w  = fmaf(dx, z4.y, ox);
            pst4[3 * g + 0] = A;
            Bq.x = fmaf(dy, z4.y, oy); Bq.y = fmaf(dz, z4.y, oz);
            Bq.z = fmaf(dx, z4.z, ox); Bq.w = fmaf(dy, z4.z, oy);
            pst4[3 * g + 1] = Bq;
            C.x  = fmaf(dz, z4.z, oz); C.y  = fmaf(dx, z4.w, ox);
            C.z  = fmaf(dy, z4.w, oy); C.w  = fmaf(dz, z4.w, oz);
            pst4[3 * g + 2] = C;
        }
    }
    __syncwarp();

    // ---- Epilogue B: coalesced LDS.128 + STG.128 copy of pts --------------
    float4* o4 = (float4*)(out_pts + (size_t)ray * (NT * 3));  // 144 x float4
    #pragma unroll
    for (int t = 0; t < 5; t++) {
        if (t < 4 || lane < 16) {
            const int m = lane + 32 * t;
            o4[m] = pst4[m];
        }
    }
}

extern "C" void kernel_launch(void* const* d_in, const int* in_sizes, int n_in,
                              void* d_out, int out_size)
{
    const float* rays_o  = (const float*)d_in[0];
    const float* rays_d  = (const float*)d_in[1];
    const float* z_vals  = (const float*)d_in[2];
    const float* weights = (const float*)d_in[3];

    const int n_rays = in_sizes[0] / 3;

    float* out_pts  = (float*)d_out;
    float* out_zall = out_pts + (size_t)n_rays * (NT * 3);
    float* out_zs   = out_zall + (size_t)n_rays * NT;

    const int blocks = (n_rays + WPB - 1) / WPB;
    importance_sampler_kernel<<<blocks, 256>>>(rays_o, rays_d, z_vals, weights,
                                               out_pts, out_zall, out_zs, n_rays);
}

// round 17
// speedup vs baseline: 1.2968x; 1.0135x over previous
#include <cuda_runtime.h>

// NeRF importance sampler — push-model, hoisted loads, branchless select epilogue.
//   inputs : rays_o[N,3], rays_d[N,3], z_vals[N,64] (sorted), weights[N,64]
//   outputs: pts[N,192,3] | z_all[N,192] | z_samples[N,128]  (flat concat)
//
// One warp per ray, 8 warps/block, 8 blocks/SM. u_j = j/127 uniform =>
// interval k owns samples j in [B_k, B_{k+1}), B_k = clamp(ceil(127*cdf_k),128).
// Lane l owns intervals 2l, 2l+1 (params in registers), generates its samples,
// scatters them into zs and into their merged zal position
// (pos = j + lo + (zvR <= v)); right edge placed at k+1 + B_k + count_lt.
// Complementary compares keep the 192 positions a permutation.
// o/d are loaded by lanes 0..5 at kernel entry into shared (latency hidden
// behind scan+generation). Epilogue: ONE syncwarp, then zs-out, zall-out and
// pts computed directly from zal with predicated component selects (no
// divergent branches, no staging round-trip). All global stores are
// warp-coalesced 128-bit except zs (128-bit too).

#define NS   64
#define NI   128
#define NT   192
#define WPB  8

__global__ __launch_bounds__(256, 8)
void importance_sampler_kernel(const float* __restrict__ rays_o,
                               const float* __restrict__ rays_d,
                               const float* __restrict__ z_vals,
                               const float* __restrict__ weights,
                               float* __restrict__ out_pts,    // [N,192,3]
                               float* __restrict__ out_zall,   // [N,192]
                               float* __restrict__ out_zs,     // [N,128]
                               int n_rays)
{
    __shared__ __align__(16) float sbuf[WPB][328];
    // per warp: zs [0,128) ; zal [128,320) ; od [320,326)

    const int warp = threadIdx.x >> 5;
    const int lane = threadIdx.x & 31;
    const int ray  = blockIdx.x * WPB + warp;
    if (ray >= n_rays) return;

    float* buf = sbuf[warp];
    float* zs  = buf;          // [0,128)
    float* zal = buf + 128;    // [128,320)
    float* od  = buf + 320;    // ox oy oz dx dy dz

    // ---- Hoisted input loads (issue everything before any compute) --------
    if (lane < 6) {
        const float v = (lane < 3) ? rays_o[3 * (size_t)ray + lane]
                                   : rays_d[3 * (size_t)ray + (lane - 3)];
        od[lane] = v;
    }
    const float2 z2 = ((const float2*)(z_vals + (size_t)ray * NS))[lane];
    const float2 w2 = ((const float2*)(weights + (size_t)ray * NS))[lane];

    // ---- Phase 1: CDF scan (all in registers) -----------------------------
    const float wnx = __shfl_down_sync(0xffffffffu, w2.x, 1);   // wrow[2l+2]

    // w[j] = weights[j+1]+1e-5, j=0..61; lane l<31 owns j=2l (wa), 2l+1 (wb)
    float wa = 0.f, wb = 0.f;
    if (lane < 31) {
        wa = w2.y + 1e-5f;
        wb = wnx  + 1e-5f;
    }
    const float local = wa + wb;
    float s = local;
    #pragma unroll
    for (int off = 1; off < 32; off <<= 1) {
        float up = __shfl_up_sync(0xffffffffu, s, off);
        if (lane >= off) s += up;
    }
    const float inv_total = 1.0f / __shfl_sync(0xffffffffu, s, 31);
    const float excl = s - local;

    // cdf[2l+1] = c1, cdf[2l+2] = c2 (valid for lane<31)
    float c1 = 0.f, c2 = 0.f;
    if (lane < 31) {
        c1 = (excl + wa) * inv_total;
        c2 = (excl + local) * inv_total;
    }

    // ---- Phase 2: per-lane interval parameters (registers only) -----------
    const float znx = __shfl_down_sync(0xffffffffu, z2.x, 1);   // zv[2l+2]
    const float m0  = 0.5f * (z2.x + z2.y);                     // mid[2l]
    const float m1  = 0.5f * (z2.y + znx);                      // mid[2l+1] (l<31)
    float cprev = __shfl_up_sync(0xffffffffu, c2, 1);           // cdf[2l]
    if (lane == 0) cprev = 0.f;
    const float mnext = __shfl_down_sync(0xffffffffu, m0, 1);   // mid[2l+2] (l<31)

    // Sample-range boundaries B (monotone since cdf strictly increases)
    const int bA = min((int)ceilf(cprev * 127.0f), 128);        // B[2l]
    int bB = 128, bC = 128;                                     // lane 31: A=[bA,128)
    float SA = 0.f, SB = 0.f;                                   // lane 31: v = mid[62]
    if (lane < 31) {
        bB = min((int)ceilf(c1 * 127.0f), 128);                 // B[2l+1]
        bC = min((int)ceilf(c2 * 127.0f), 128);                 // B[2l+2]
        float dA = c1 - cprev; if (dA < 1e-5f) dA = 1.0f;
        float dB = c2 - c1;    if (dB < 1e-5f) dB = 1.0f;
        SA = (m1 - m0) / dA;
        SB = (mnext - m1) / dB;
    }

    // ---- Phase 3: generate samples, scatter into zs and merged zal --------
    if (lane == 0) zal[0] = z2.x;              // zv[0] always ranks first

    // interval k = 2l: samples [bA, bB), right edge zv[2l+1] = z2.y, lo = 2l+1
    {
        int cnt_ge = 0;
        for (int j = bA; j < bB; j++) {
            const float u = (float)j * (1.0f / 127.0f);
            const float v = fmaf(u - cprev, SA, m0);
            zs[j] = v;
            const int ge = (z2.y <= v) ? 1 : 0;
            cnt_ge += ge;
            zal[j + 2 * lane + 1 + ge] = v;
        }
        // place zv[2l+1]: pos = (2l+1) + B[2l] + #{v < zv[2l+1]}
        zal[2 * lane + 1 + bA + (bB - bA) - cnt_ge] = z2.y;
    }
    // interval k = 2l+1 (lane<31): samples [bB, bC), right edge zv[2l+2] = znx
    {
        int cnt_ge = 0;
        for (int j = bB; j < bC; j++) {
            const float u = (float)j * (1.0f / 127.0f);
            const float v = fmaf(u - c1, SB, m1);
            zs[j] = v;
            const int ge = (znx <= v) ? 1 : 0;
            cnt_ge += ge;
            zal[j + 2 * lane + 2 + ge] = v;
        }
        if (lane < 31)
            zal[2 * lane + 2 + bB + (bC - bB) - cnt_ge] = znx;
    }
    __syncwarp();   // the ONLY epilogue barrier: everything below is reads

    // ---- z_samples + z_all out (float4, coalesced) ------------------------
    ((float4*)(out_zs + (size_t)ray * NI))[lane] = ((const float4*)zs)[lane];
    {
        float4* a4 = (float4*)(out_zall + (size_t)ray * NT);   // 48 x float4
        a4[lane] = ((const float4*)zal)[lane];
        if (lane < 16) a4[32 + lane] = ((const float4*)zal)[32 + lane];
    }

    // ---- pts directly from zal: branchless selects, coalesced STG.128 -----
    const float ox = od[0], oy = od[1], oz = od[2];
    const float dx = od[3], dy = od[4], dz = od[5];

    float4* o4 = (float4*)(out_pts + (size_t)ray * (NT * 3));  // 144 x float4
    #pragma unroll
    for (int t = 0; t < 5; t++) {
        if (t < 4 || lane < 16) {
            const int m  = lane + 32 * t;          // output float4 id, 0..143
            const int r  = m % 3;
            const int ka = (4 * m - r) / 3;        // first point touched
            const float za = zal[ka];
            const float zb = zal[ka + 1];          // ka+1 <= 191
            const float Ax = fmaf(dx, za, ox);
            const float Ay = fmaf(dy, za, oy);
            const float Az = fmaf(dz, za, oz);
            const float Bx = fmaf(dx, zb, ox);
            const float By = fmaf(dy, zb, oy);
            const float Bz = fmaf(dz, zb, oz);
            // r==0: (Ax,Ay,Az,Bx)  r==1: (Ay,Az,Bx,By)  r==2: (Az,Bx,By,Bz)
            const bool r0 = (r == 0), r1 = (r == 1);
            float4 o;
            o.x = r0 ? Ax : (r1 ? Ay : Az);
            o.y = r0 ? Ay : (r1 ? Az : Bx);
            o.z = r0 ? Az : (r1 ? Bx : By);
            o.w = r0 ? Bx : (r1 ? By : Bz);
            o4[m] = o;                              // coalesced
        }
    }
}

extern "C" void kernel_launch(void* const* d_in, const int* in_sizes, int n_in,
                              void* d_out, int out_size)
{
    const float* rays_o  = (const float*)d_in[0];
    const float* rays_d  = (const float*)d_in[1];
    const float* z_vals  = (const float*)d_in[2];
    const float* weights = (const float*)d_in[3];

    const int n_rays = in_sizes[0] / 3;

    float* out_pts  = (float*)d_out;
    float* out_zall = out_pts + (size_t)n_rays * (NT * 3);
    float* out_zs   = out_zall + (size_t)n_rays * NT;

    const int blocks = (n_rays + WPB - 1) / WPB;
    importance_sampler_kernel<<<blocks, 256>>>(rays_o, rays_d, z_vals, weights,
                                               out_pts, out_zall, out_zs, n_rays);
}